// round 1
// baseline (speedup 1.0000x reference)
#include <cuda_runtime.h>

#define B_ 16
#define O_ 32
#define CPO_ 4
#define H_ 128
#define W_ 128
#define S_ 16
#define T_ 32
#define PAD_ 64
#define WP_ 256
#define HW_ (H_*W_)

typedef unsigned long long ull;

// Scratch: transposed+padded input, (B,O,H,WP) with CPO innermost as float4.
// Zero pad columns [0,64) and [192,256) so horizontal bounds checks vanish.
__device__ float4 g_xT[(size_t)B_ * O_ * H_ * WP_];
__device__ int2   g_shift[O_ * S_];
__device__ float4 g_wts[O_ * S_];

// ---------------------------------------------------------------------------
// Kernel 1: per-(offset,sample) parameters. 32 threads, one per offset.
// Computes integer shift (iy,ix) + 4 merged bilinear*gaussian weights,
// then sorts the 16 samples by (iy,ix) for L1 locality in the main kernel.
// ---------------------------------------------------------------------------
__global__ void param_kernel(const float* __restrict__ ox, const float* __restrict__ oy,
                             const float* __restrict__ ua, const float* __restrict__ us,
                             const float* __restrict__ ar, const float* __restrict__ sr)
{
    int o = threadIdx.x;
    if (o >= O_) return;
    const float MINA = 0.024979197860971382f;   // atan2(0.5,10)/2
    const float PIF  = 3.14159265358979323846f;
    const float EPSF = 1.1920928955078125e-07f;

    float astd = 1.f / (1.f + expf(-ar[o])) * (PIF - MINA) + MINA;
    float sstd = 1.f / (1.f + expf(-sr[o])) * (5.0f - 0.2f) + 0.2f;
    float high_a = fminf(astd * 3.f, PIF);
    float s3 = sstd * 3.f;
    float ia  = 0.5f / (astd * astd + EPSF);
    float isc = 0.5f / (sstd * sstd + EPSF);

    float an[S_], sc[S_], wt[S_];
    float sum = 0.f;
    for (int t = 0; t < T_; t++) {
        float a = ua[o * T_ + t] * high_a;
        float s = us[o * T_ + t] * s3;
        float w = expf(-(a * a * ia + s * s * isc));
        sum += w;
        if (t < S_) { an[t] = a; sc[t] = s; wt[t] = w; }
    }
    float inv = 2.f / (sum + EPSF);   // * NUM_TOTAL/NUM_SAMPLE

    float oxv = ox[o], oyv = oy[o];
    float dist = sqrtf(oxv * oxv + oyv * oyv);
    float a0 = atan2f(oyv, oxv);

    int key[S_], kiy[S_], kix[S_];
    float4 kw[S_];
    for (int s = 0; s < S_; s++) {
        float w  = wt[s] * inv;
        float nd = dist + sc[s];
        float na = a0 + an[s];
        float dx = nd * cosf(na);
        float dy = nd * sinf(na);
        float fy = floorf(dy), fx = floorf(dx);
        float ay = dy - fy,  ax = dx - fx;
        int iy = (int)fy, ix = (int)fx;
        iy = max(-PAD_, min(PAD_ - 1, iy));   // safety clamp (never hit w/ this data)
        ix = max(-PAD_, min(PAD_ - 1, ix));
        float wy0 = 1.f - ay, wx0 = 1.f - ax;
        kw[s]  = make_float4(w * wy0 * wx0, w * wy0 * ax, w * ay * wx0, w * ay * ax);
        kiy[s] = iy; kix[s] = ix;
        key[s] = ((iy + PAD_) << 8) | (ix + PAD_);
    }
    // insertion sort by (iy,ix) — sum order is irrelevant, locality is not
    for (int i = 1; i < S_; i++) {
        int k = key[i], yy = kiy[i], xx = kix[i]; float4 ww = kw[i];
        int j = i - 1;
        while (j >= 0 && key[j] > k) {
            key[j+1] = key[j]; kiy[j+1] = kiy[j]; kix[j+1] = kix[j]; kw[j+1] = kw[j];
            j--;
        }
        key[j+1] = k; kiy[j+1] = yy; kix[j+1] = xx; kw[j+1] = ww;
    }
    for (int s = 0; s < S_; s++) {
        g_shift[o * S_ + s] = make_int2(kiy[s], kix[s]);
        g_wts[o * S_ + s]   = kw[s];
    }
}

// ---------------------------------------------------------------------------
// Kernel 2: transpose (B,O,CPO,H,W) -> (B,O,H,WP,CPO) float4, zero-padded cols.
// Reads coalesced along w per channel plane; writes coalesced float4.
// ---------------------------------------------------------------------------
__global__ void transpose_kernel(const float* __restrict__ x)
{
    int idx  = blockIdx.x * 256 + threadIdx.x;      // < B*O*H*WP
    int xp   = idx & (WP_ - 1);
    int rest = idx >> 8;                            // bo*H + h
    int h    = rest & (H_ - 1);
    int bo   = rest >> 7;
    float4 v = make_float4(0.f, 0.f, 0.f, 0.f);
    int w = xp - PAD_;
    if ((unsigned)w < (unsigned)W_) {
        const float* p = x + (((size_t)bo * CPO_) * H_ + h) * W_ + w;
        v.x = p[0];
        v.y = p[HW_];
        v.z = p[2 * HW_];
        v.w = p[3 * HW_];
    }
    g_xT[idx] = v;
}

// ---------------------------------------------------------------------------
// Packed fp32x2 helpers (sm_103a): one FFMA-pipe op processes 2 channels.
// ---------------------------------------------------------------------------
__device__ __forceinline__ ull pk2(float f) {
    ull r; asm("mov.b64 %0,{%1,%1};" : "=l"(r) : "f"(f)); return r;
}
__device__ __forceinline__ void fma2(ull& d, ull a, ull b) {
    asm("fma.rn.f32x2 %0,%1,%2,%0;" : "+l"(d) : "l"(a), "l"(b));
}
__device__ __forceinline__ void unpk(ull v, float& lo, float& hi) {
    asm("mov.b64 {%0,%1},%2;" : "=f"(lo), "=f"(hi) : "l"(v));
}

// ---------------------------------------------------------------------------
// Kernel 3: main gather. Block = 256 threads = 64 w-threads x 4 h-groups.
// Each thread: KH=4 x KW=2 pixels x 4 channels. Per sample: 5x3 f4 window
// with rolling row buffers (vertical+horizontal tap reuse in registers).
// Rows out of [0,H) handled by a warp-uniform branch (h-group == warp group).
// ---------------------------------------------------------------------------
__global__ void __launch_bounds__(256, 2) disp_kernel(float* __restrict__ out)
{
    __shared__ int2   s_sh[S_];
    __shared__ float4 s_w[S_];
    const int tid = threadIdx.x;
    const int o = blockIdx.y, b = blockIdx.z;
    const int bo = b * O_ + o;
    if (tid < S_) { s_sh[tid] = g_shift[o * S_ + tid]; s_w[tid] = g_wts[o * S_ + tid]; }
    __syncthreads();

    const int wx = tid & 63, hy = tid >> 6;
    const int hbase = blockIdx.x * 16 + hy * 4;
    const int wbase = wx * 2;
    const ulonglong2* __restrict__ plane =
        reinterpret_cast<const ulonglong2*>(g_xT) + (size_t)bo * (H_ * WP_);

    ull acc[4][2][2];
    #pragma unroll
    for (int i = 0; i < 4; i++)
        #pragma unroll
        for (int j = 0; j < 2; j++) { acc[i][j][0] = 0ull; acc[i][j][1] = 0ull; }

#define LOADR(R0, R1, R2, yy) do {                                          \
        int _y = (yy);                                                      \
        if ((unsigned)_y < (unsigned)H_) {                                  \
            const ulonglong2* _p = pr + _y * WP_;                           \
            R0 = _p[0]; R1 = _p[1]; R2 = _p[2];                             \
        } else { R0.x = 0ull; R0.y = 0ull; R1 = R0; R2 = R0; }              \
    } while (0)

#define TAPS(T0, T1, T2, U0, U1, U2, kh) do {                               \
        fma2(acc[kh][0][0], T0.x, W00); fma2(acc[kh][0][1], T0.y, W00);     \
        fma2(acc[kh][0][0], T1.x, W01); fma2(acc[kh][0][1], T1.y, W01);     \
        fma2(acc[kh][0][0], U0.x, W10); fma2(acc[kh][0][1], U0.y, W10);     \
        fma2(acc[kh][0][0], U1.x, W11); fma2(acc[kh][0][1], U1.y, W11);     \
        fma2(acc[kh][1][0], T1.x, W00); fma2(acc[kh][1][1], T1.y, W00);     \
        fma2(acc[kh][1][0], T2.x, W01); fma2(acc[kh][1][1], T2.y, W01);     \
        fma2(acc[kh][1][0], U1.x, W10); fma2(acc[kh][1][1], U1.y, W10);     \
        fma2(acc[kh][1][0], U2.x, W11); fma2(acc[kh][1][1], U2.y, W11);     \
    } while (0)

    #pragma unroll 2
    for (int s = 0; s < S_; s++) {
        const int2   sh = s_sh[s];
        const float4 wv = s_w[s];
        const ull W00 = pk2(wv.x), W01 = pk2(wv.y), W10 = pk2(wv.z), W11 = pk2(wv.w);
        const int xc = wbase + sh.y + PAD_;
        const int y0 = hbase + sh.x;
        const ulonglong2* __restrict__ pr = plane + xc;

        ulonglong2 A0, A1, A2, B0, B1, B2;
        LOADR(A0, A1, A2, y0);
        LOADR(B0, B1, B2, y0 + 1); TAPS(A0, A1, A2, B0, B1, B2, 0);
        LOADR(A0, A1, A2, y0 + 2); TAPS(B0, B1, B2, A0, A1, A2, 1);
        LOADR(B0, B1, B2, y0 + 3); TAPS(A0, A1, A2, B0, B1, B2, 2);
        LOADR(A0, A1, A2, y0 + 4); TAPS(B0, B1, B2, A0, A1, A2, 3);
    }
#undef LOADR
#undef TAPS

    float* __restrict__ ob = out + (size_t)bo * CPO_ * HW_;
    #pragma unroll
    for (int kh = 0; kh < 4; kh++) {
        const int h = hbase + kh;
        #pragma unroll
        for (int kw = 0; kw < 2; kw++) {
            const int w = wbase + kw;
            const size_t pix = (size_t)h * W_ + w;
            float c0, c1, c2, c3;
            unpk(acc[kh][kw][0], c0, c1);
            unpk(acc[kh][kw][1], c2, c3);
            ob[pix]           = c0;
            ob[HW_ + pix]     = c1;
            ob[2 * HW_ + pix] = c2;
            ob[3 * HW_ + pix] = c3;
        }
    }
}

extern "C" void kernel_launch(void* const* d_in, const int* in_sizes, int n_in,
                              void* d_out, int out_size)
{
    const float* x  = (const float*)d_in[0];
    const float* ox = (const float*)d_in[1];
    const float* oy = (const float*)d_in[2];
    const float* ua = (const float*)d_in[3];
    const float* us = (const float*)d_in[4];
    const float* ar = (const float*)d_in[5];
    const float* sr = (const float*)d_in[6];
    float* out = (float*)d_out;

    param_kernel<<<1, 32>>>(ox, oy, ua, us, ar, sr);
    transpose_kernel<<<(B_ * O_ * H_ * WP_) / 256, 256>>>(x);
    disp_kernel<<<dim3(H_ / 16, O_, B_), 256>>>(out);
}

// round 2
// speedup vs baseline: 1.2581x; 1.2581x over previous
#include <cuda_runtime.h>
#include <cuda_fp16.h>

#define B_ 16
#define O_ 32
#define CPO_ 4
#define H_ 128
#define W_ 128
#define S_ 16
#define T_ 32
#define HW_ (H_*W_)

typedef unsigned long long ull;

// Scratch: transposed input, (B,O,H,W) with CPO innermost as 4x fp16 (uint2).
__device__ uint2  g_xT[(size_t)B_ * O_ * H_ * W_];
__device__ int2   g_shift[O_ * S_];
__device__ float4 g_wts[O_ * S_];

// ---------------------------------------------------------------------------
// Kernel 1: per-(offset,sample) parameters. 32 warps = 1 per offset,
// lane t computes the t-th Gaussian weight (warp-reduced sum), lanes 0..15
// compute the per-sample shift + merged weights, then rank-scatter by (iy,ix)
// so the main kernel visits samples in locality order.
// ---------------------------------------------------------------------------
__global__ void param_kernel(const float* __restrict__ ox, const float* __restrict__ oy,
                             const float* __restrict__ ua, const float* __restrict__ us,
                             const float* __restrict__ ar, const float* __restrict__ sr)
{
    const int lane = threadIdx.x;
    const int o    = threadIdx.y;
    const float MINA = 0.024979197860971382f;   // atan2(0.5,10)/2
    const float PIF  = 3.14159265358979323846f;
    const float EPSF = 1.1920928955078125e-07f;

    float astd = 1.f / (1.f + expf(-ar[o])) * (PIF - MINA) + MINA;
    float sstd = 1.f / (1.f + expf(-sr[o])) * (5.0f - 0.2f) + 0.2f;
    float high_a = fminf(astd * 3.f, PIF);
    float s3 = sstd * 3.f;
    float ia  = 0.5f / (astd * astd + EPSF);
    float isc = 0.5f / (sstd * sstd + EPSF);

    float a = ua[o * T_ + lane] * high_a;
    float s = us[o * T_ + lane] * s3;
    float w = expf(-(a * a * ia + s * s * isc));
    float sum = w;
    #pragma unroll
    for (int d = 16; d; d >>= 1) sum += __shfl_xor_sync(0xffffffffu, sum, d);
    float inv = 2.f / (sum + EPSF);   // * NUM_TOTAL/NUM_SAMPLE

    if (lane < S_) {
        float oxv = ox[o], oyv = oy[o];
        float dist = sqrtf(oxv * oxv + oyv * oyv);
        float a0 = atan2f(oyv, oxv);

        float ws = w * inv;
        float nd = dist + s;
        float na = a0 + a;
        float dx = nd * cosf(na);
        float dy = nd * sinf(na);
        float fy = floorf(dy), fx = floorf(dx);
        float ay = dy - fy,  axf = dx - fx;
        int iy = max(-H_, min(H_ - 1, (int)fy));
        int ix = max(-W_, min(W_ - 1, (int)fx));
        float wy0 = 1.f - ay, wx0 = 1.f - axf;
        int key = ((iy + 256) << 10) | (ix + 256);

        int rank = 0;
        #pragma unroll
        for (int j = 0; j < S_; j++) {
            int kj = __shfl_sync(0x0000ffffu, key, j);
            rank += (kj < key) || (kj == key && j < lane);
        }
        g_shift[o * S_ + rank] = make_int2(iy, ix);
        g_wts[o * S_ + rank]   = make_float4(ws * wy0 * wx0, ws * wy0 * axf,
                                             ws * ay * wx0,  ws * ay * axf);
    }
}

// ---------------------------------------------------------------------------
// Kernel 2: transpose (B,O,CPO,H,W) fp32 -> (B,O,H,W) x 4ch fp16 (uint2).
// Each thread handles 4 w-pixels: 4x float4 coalesced reads, 32B write.
// ---------------------------------------------------------------------------
__global__ void transpose_kernel(const float* __restrict__ x)
{
    int idx  = blockIdx.x * 256 + threadIdx.x;      // pixel-group of 4
    int wg   = idx & (W_/4 - 1);
    int rest = idx >> 5;                            // bo*H + h
    size_t base = ((size_t)(rest >> 7) * CPO_ * H_ + (rest & (H_-1))) * W_ + wg * 4;

    float4 c0 = *(const float4*)(x + base);
    float4 c1 = *(const float4*)(x + base + HW_);
    float4 c2 = *(const float4*)(x + base + 2 * HW_);
    float4 c3 = *(const float4*)(x + base + 3 * HW_);

    uint4 o0, o1;
    __half2 h;
    h = __floats2half2_rn(c0.x, c1.x); o0.x = *(unsigned*)&h;
    h = __floats2half2_rn(c2.x, c3.x); o0.y = *(unsigned*)&h;
    h = __floats2half2_rn(c0.y, c1.y); o0.z = *(unsigned*)&h;
    h = __floats2half2_rn(c2.y, c3.y); o0.w = *(unsigned*)&h;
    h = __floats2half2_rn(c0.z, c1.z); o1.x = *(unsigned*)&h;
    h = __floats2half2_rn(c2.z, c3.z); o1.y = *(unsigned*)&h;
    h = __floats2half2_rn(c0.w, c1.w); o1.z = *(unsigned*)&h;
    h = __floats2half2_rn(c2.w, c3.w); o1.w = *(unsigned*)&h;

    uint4* dst = reinterpret_cast<uint4*>(g_xT) + idx * 2;
    dst[0] = o0;
    dst[1] = o1;
}

// ---------------------------------------------------------------------------
// Packed fp32x2 helpers (sm_103a).
// ---------------------------------------------------------------------------
__device__ __forceinline__ ull pk2(float f) {
    ull r; asm("mov.b64 %0,{%1,%1};" : "=l"(r) : "f"(f)); return r;
}
__device__ __forceinline__ void fma2(ull& d, ull a, ull b) {
    asm("fma.rn.f32x2 %0,%1,%2,%0;" : "+l"(d) : "l"(a), "l"(b));
}
__device__ __forceinline__ void unpk(ull v, float& lo, float& hi) {
    asm("mov.b64 {%0,%1},%2;" : "=f"(lo), "=f"(hi) : "l"(v));
}
// half2 (2 channels) -> packed float2 in a 64-bit reg
__device__ __forceinline__ ull h2f2(unsigned h) {
    ull r;
    asm("{\n\t.reg .b16 a,b;\n\t.reg .f32 lo,hi;\n\t"
        "mov.b32 {a,b},%1;\n\tcvt.f32.f16 lo,a;\n\tcvt.f32.f16 hi,b;\n\t"
        "mov.b64 %0,{lo,hi};\n\t}" : "=l"(r) : "r"(h));
    return r;
}

// ---------------------------------------------------------------------------
// Kernel 3: main gather. Block = 256 threads = 64 w-threads x 4 h-groups.
// Each thread: KH=4 x KW=2 pixels x 4 channels (fp16 loads, fp32x2 math).
// Per sample: 5-row x 3-col uint2 window with rolling row buffers.
// Rows: warp-uniform branch. Cols: 3 per-sample predicates (no padding).
// ---------------------------------------------------------------------------
__global__ void __launch_bounds__(256, 2) disp_kernel(float* __restrict__ out)
{
    __shared__ int2   s_sh[S_];
    __shared__ float4 s_w[S_];
    const int tid = threadIdx.x;
    const int o = blockIdx.y, b = blockIdx.z;
    const int bo = b * O_ + o;
    if (tid < S_) { s_sh[tid] = g_shift[o * S_ + tid]; s_w[tid] = g_wts[o * S_ + tid]; }
    __syncthreads();

    const int wx = tid & 63, hy = tid >> 6;
    const int hbase = blockIdx.x * 16 + hy * 4;
    const int wbase = wx * 2;
    const uint2* __restrict__ plane = g_xT + (size_t)bo * HW_;

    ull acc[4][2][2];
    #pragma unroll
    for (int i = 0; i < 4; i++)
        #pragma unroll
        for (int j = 0; j < 2; j++) { acc[i][j][0] = 0ull; acc[i][j][1] = 0ull; }

// Load row yy: 3 predicated uint2 loads, convert to 6 packed-f32x2 regs.
#define LOADR(R, yy) do {                                                   \
        int _y = (yy);                                                      \
        if ((unsigned)_y < (unsigned)H_) {                                  \
            const uint2* _p = pr + _y * W_;                                 \
            uint2 _c0 = make_uint2(0u,0u), _c1 = _c0, _c2 = _c0;            \
            if (v0) _c0 = _p[0];                                            \
            if (v1) _c1 = _p[1];                                            \
            if (v2) _c2 = _p[2];                                            \
            R[0] = h2f2(_c0.x); R[1] = h2f2(_c0.y);                         \
            R[2] = h2f2(_c1.x); R[3] = h2f2(_c1.y);                         \
            R[4] = h2f2(_c2.x); R[5] = h2f2(_c2.y);                         \
        } else {                                                            \
            R[0]=0ull; R[1]=0ull; R[2]=0ull; R[3]=0ull; R[4]=0ull; R[5]=0ull; \
        }                                                                   \
    } while (0)

// Tt = top row buffer, Ut = bottom row buffer (6 packed regs each).
#define TAPS(Tt, Ut, kh) do {                                               \
        fma2(acc[kh][0][0], Tt[0], W00); fma2(acc[kh][0][1], Tt[1], W00);   \
        fma2(acc[kh][0][0], Tt[2], W01); fma2(acc[kh][0][1], Tt[3], W01);   \
        fma2(acc[kh][0][0], Ut[0], W10); fma2(acc[kh][0][1], Ut[1], W10);   \
        fma2(acc[kh][0][0], Ut[2], W11); fma2(acc[kh][0][1], Ut[3], W11);   \
        fma2(acc[kh][1][0], Tt[2], W00); fma2(acc[kh][1][1], Tt[3], W00);   \
        fma2(acc[kh][1][0], Tt[4], W01); fma2(acc[kh][1][1], Tt[5], W01);   \
        fma2(acc[kh][1][0], Ut[2], W10); fma2(acc[kh][1][1], Ut[3], W10);   \
        fma2(acc[kh][1][0], Ut[4], W11); fma2(acc[kh][1][1], Ut[5], W11);   \
    } while (0)

    #pragma unroll 2
    for (int s = 0; s < S_; s++) {
        const int2   sh = s_sh[s];
        const float4 wv = s_w[s];
        const ull W00 = pk2(wv.x), W01 = pk2(wv.y), W10 = pk2(wv.z), W11 = pk2(wv.w);
        const int xc = wbase + sh.y;
        const bool v0 = (unsigned)xc       < (unsigned)W_;
        const bool v1 = (unsigned)(xc + 1) < (unsigned)W_;
        const bool v2 = (unsigned)(xc + 2) < (unsigned)W_;
        const int y0 = hbase + sh.x;
        const uint2* __restrict__ pr = plane + xc;

        ull A[6], Bv[6];
        LOADR(A,  y0);
        LOADR(Bv, y0 + 1); TAPS(A, Bv, 0);
        LOADR(A,  y0 + 2); TAPS(Bv, A, 1);
        LOADR(Bv, y0 + 3); TAPS(A, Bv, 2);
        LOADR(A,  y0 + 4); TAPS(Bv, A, 3);
    }
#undef LOADR
#undef TAPS

    float* __restrict__ ob = out + (size_t)bo * CPO_ * HW_;
    #pragma unroll
    for (int kh = 0; kh < 4; kh++) {
        const int h = hbase + kh;
        #pragma unroll
        for (int kw = 0; kw < 2; kw++) {
            const int w = wbase + kw;
            const size_t pix = (size_t)h * W_ + w;
            float c0, c1, c2, c3;
            unpk(acc[kh][kw][0], c0, c1);
            unpk(acc[kh][kw][1], c2, c3);
            ob[pix]           = c0;
            ob[HW_ + pix]     = c1;
            ob[2 * HW_ + pix] = c2;
            ob[3 * HW_ + pix] = c3;
        }
    }
}

extern "C" void kernel_launch(void* const* d_in, const int* in_sizes, int n_in,
                              void* d_out, int out_size)
{
    const float* x  = (const float*)d_in[0];
    const float* ox = (const float*)d_in[1];
    const float* oy = (const float*)d_in[2];
    const float* ua = (const float*)d_in[3];
    const float* us = (const float*)d_in[4];
    const float* ar = (const float*)d_in[5];
    const float* sr = (const float*)d_in[6];
    float* out = (float*)d_out;

    param_kernel<<<1, dim3(32, 32)>>>(ox, oy, ua, us, ar, sr);
    transpose_kernel<<<(B_ * O_ * H_ * W_ / 4) / 256, 256>>>(x);
    disp_kernel<<<dim3(H_ / 16, O_, B_), 256>>>(out);
}

// round 3
// speedup vs baseline: 1.7955x; 1.4271x over previous
#include <cuda_runtime.h>
#include <cuda_fp16.h>

#define B_ 16
#define O_ 32
#define CPO_ 4
#define H_ 128
#define W_ 128
#define S_ 16
#define T_ 32
#define HW_ (H_*W_)
#define NT_ ((B_*O_*H_*W_/4)/256)   /* transpose blocks = 8192 */

typedef unsigned long long ull;

// Scratch: transposed input, (B,O,H,W) with CPO innermost as 4x fp16 (uint2).
__device__ uint2 g_xT[(size_t)B_ * O_ * H_ * W_];
__device__ int2  g_shift[O_ * S_];
__device__ uint4 g_wtsh[O_ * S_];   // 4 half2-broadcast weights (W00,W01,W10,W11)

// ---------------------------------------------------------------------------
// packed helpers
// ---------------------------------------------------------------------------
__device__ __forceinline__ void add2(ull& d, ull v) {
    asm("add.rn.f32x2 %0,%0,%1;" : "+l"(d) : "l"(v));
}
__device__ __forceinline__ void unpk(ull v, float& lo, float& hi) {
    asm("mov.b64 {%0,%1},%2;" : "=f"(lo), "=f"(hi) : "l"(v));
}
// half2 -> packed float2 in one 64-bit reg
__device__ __forceinline__ ull h2f2(__half2 h) {
    unsigned u = *reinterpret_cast<unsigned*>(&h);
    ull r;
    asm("{\n\t.reg .b16 a,b;\n\t.reg .f32 lo,hi;\n\t"
        "mov.b32 {a,b},%1;\n\tcvt.f32.f16 lo,a;\n\tcvt.f32.f16 hi,b;\n\t"
        "mov.b64 %0,{lo,hi};\n\t}" : "=l"(r) : "r"(u));
    return r;
}
__device__ __forceinline__ __half2 u2h(unsigned u) {
    return *reinterpret_cast<__half2*>(&u);
}

// ---------------------------------------------------------------------------
// Kernel 1 (fused): blocks [0,NT_) transpose, blocks [NT_, NT_+4) params.
// Transpose: (B,O,CPO,H,W) fp32 -> (B,O,H,W) x 4ch fp16 (uint2).
// Params: 8 warps/block = 8 offsets; lane t = t-th gaussian weight,
// lanes 0..15 finalize samples, rank-scatter by (iy,ix) for locality.
// ---------------------------------------------------------------------------
__global__ void pre_kernel(const float* __restrict__ x,
                           const float* __restrict__ ox, const float* __restrict__ oy,
                           const float* __restrict__ ua, const float* __restrict__ us,
                           const float* __restrict__ ar, const float* __restrict__ sr)
{
    if (blockIdx.x < NT_) {
        int idx  = blockIdx.x * 256 + threadIdx.x;      // pixel-group of 4
        int wg   = idx & (W_/4 - 1);
        int rest = idx >> 5;                            // bo*H + h
        size_t base = ((size_t)(rest >> 7) * CPO_ * H_ + (rest & (H_-1))) * W_ + wg * 4;

        float4 c0 = *(const float4*)(x + base);
        float4 c1 = *(const float4*)(x + base + HW_);
        float4 c2 = *(const float4*)(x + base + 2 * HW_);
        float4 c3 = *(const float4*)(x + base + 3 * HW_);

        uint4 o0, o1;
        __half2 h;
        h = __floats2half2_rn(c0.x, c1.x); o0.x = *(unsigned*)&h;
        h = __floats2half2_rn(c2.x, c3.x); o0.y = *(unsigned*)&h;
        h = __floats2half2_rn(c0.y, c1.y); o0.z = *(unsigned*)&h;
        h = __floats2half2_rn(c2.y, c3.y); o0.w = *(unsigned*)&h;
        h = __floats2half2_rn(c0.z, c1.z); o1.x = *(unsigned*)&h;
        h = __floats2half2_rn(c2.z, c3.z); o1.y = *(unsigned*)&h;
        h = __floats2half2_rn(c0.w, c1.w); o1.z = *(unsigned*)&h;
        h = __floats2half2_rn(c2.w, c3.w); o1.w = *(unsigned*)&h;

        uint4* dst = reinterpret_cast<uint4*>(g_xT) + (size_t)idx * 2;
        dst[0] = o0;
        dst[1] = o1;
        return;
    }

    // ---- param path ----
    const int lane = threadIdx.x & 31;
    const int o    = (blockIdx.x - NT_) * 8 + (threadIdx.x >> 5);
    const float MINA = 0.024979197860971382f;
    const float PIF  = 3.14159265358979323846f;
    const float EPSF = 1.1920928955078125e-07f;

    float astd = 1.f / (1.f + expf(-ar[o])) * (PIF - MINA) + MINA;
    float sstd = 1.f / (1.f + expf(-sr[o])) * (5.0f - 0.2f) + 0.2f;
    float high_a = fminf(astd * 3.f, PIF);
    float s3 = sstd * 3.f;
    float ia  = 0.5f / (astd * astd + EPSF);
    float isc = 0.5f / (sstd * sstd + EPSF);

    float a = ua[o * T_ + lane] * high_a;
    float s = us[o * T_ + lane] * s3;
    float w = expf(-(a * a * ia + s * s * isc));
    float sum = w;
    #pragma unroll
    for (int d = 16; d; d >>= 1) sum += __shfl_xor_sync(0xffffffffu, sum, d);
    float inv = 2.f / (sum + EPSF);

    if (lane < S_) {
        float oxv = ox[o], oyv = oy[o];
        float dist = sqrtf(oxv * oxv + oyv * oyv);
        float a0 = atan2f(oyv, oxv);

        float ws = w * inv;
        float nd = dist + s;
        float na = a0 + a;
        float dx = nd * cosf(na);
        float dy = nd * sinf(na);
        float fy = floorf(dy), fx = floorf(dx);
        float ay = dy - fy,  axf = dx - fx;
        int iy = max(-H_, min(H_ - 1, (int)fy));
        int ix = max(-W_, min(W_ - 1, (int)fx));
        float wy0 = 1.f - ay, wx0 = 1.f - axf;
        int key = ((iy + 256) << 10) | (ix + 256);

        int rank = 0;
        #pragma unroll
        for (int j = 0; j < S_; j++) {
            int kj = __shfl_sync(0x0000ffffu, key, j);
            rank += (kj < key) || (kj == key && j < lane);
        }
        __half2 h00 = __float2half2_rn(ws * wy0 * wx0);
        __half2 h01 = __float2half2_rn(ws * wy0 * axf);
        __half2 h10 = __float2half2_rn(ws * ay * wx0);
        __half2 h11 = __float2half2_rn(ws * ay * axf);
        g_shift[o * S_ + rank] = make_int2(iy, ix);
        g_wtsh[o * S_ + rank]  = make_uint4(*(unsigned*)&h00, *(unsigned*)&h01,
                                            *(unsigned*)&h10, *(unsigned*)&h11);
    }
}

// ---------------------------------------------------------------------------
// Kernel 2: main gather.
// Block = 256 = 8 warps. Warp covers 64 consecutive pixels (half = warp&1),
// lane owns pixels (l, l+32); 4 row-groups (hy = warp>>1) x KH=4 rows.
// Loads: per sample-row, 4 fully-coalesced predicated LDG.64 (fp16x4).
// Inner 4-tap combine in HFMA2 (fp16), flushed once/sample to fp32x2 acc.
// ---------------------------------------------------------------------------
struct Rw { uint2 a0, a1, b0, b1; };

__device__ __forceinline__ Rw loadRow(const uint2* __restrict__ pr, int y,
                                      bool v0, bool v0n, bool v1, bool v1n)
{
    Rw r;
    r.a0 = make_uint2(0u,0u); r.a1 = r.a0; r.b0 = r.a0; r.b1 = r.a0;
    bool yv = (unsigned)y < (unsigned)H_;
    const uint2* p = pr + y * W_;
    if (v0 & yv)  r.a0 = p[0];
    if (v0n & yv) r.a1 = p[1];
    if (v1 & yv)  r.b0 = p[32];
    if (v1n & yv) r.b1 = p[33];
    return r;
}

__device__ __forceinline__ void tap4(ull* acc, uint2 t0, uint2 t1, uint2 u0, uint2 u1,
                                     __half2 w00, __half2 w01, __half2 w10, __half2 w11)
{
    __half2 h0 = __hmul2(u2h(t0.x), w00);
    h0 = __hfma2(u2h(t1.x), w01, h0);
    h0 = __hfma2(u2h(u0.x), w10, h0);
    h0 = __hfma2(u2h(u1.x), w11, h0);
    __half2 h1 = __hmul2(u2h(t0.y), w00);
    h1 = __hfma2(u2h(t1.y), w01, h1);
    h1 = __hfma2(u2h(u0.y), w10, h1);
    h1 = __hfma2(u2h(u1.y), w11, h1);
    add2(acc[0], h2f2(h0));
    add2(acc[1], h2f2(h1));
}

__global__ void __launch_bounds__(256, 2) disp_kernel(float* __restrict__ out)
{
    __shared__ int2  s_sh[S_];
    __shared__ uint4 s_w[S_];
    const int tid = threadIdx.x;
    const int o = blockIdx.y, b = blockIdx.z;
    const int bo = b * O_ + o;
    if (tid < S_) { s_sh[tid] = g_shift[o * S_ + tid]; s_w[tid] = g_wtsh[o * S_ + tid]; }
    __syncthreads();

    const int lane = tid & 31, warp = tid >> 5;
    const int half = warp & 1, hy = warp >> 1;
    const int hbase = blockIdx.x * 16 + hy * 4;
    const int wpix  = half * 64 + lane;
    const uint2* __restrict__ plane = g_xT + (size_t)bo * HW_;

    ull acc[4][2][2];
    #pragma unroll
    for (int i = 0; i < 4; i++)
        #pragma unroll
        for (int g = 0; g < 2; g++) { acc[i][g][0] = 0ull; acc[i][g][1] = 0ull; }

    #pragma unroll 2
    for (int s = 0; s < S_; s++) {
        const int2  sh = s_sh[s];
        const uint4 wv = s_w[s];
        const __half2 w00 = u2h(wv.x), w01 = u2h(wv.y), w10 = u2h(wv.z), w11 = u2h(wv.w);
        const int cl = wpix + sh.y;
        const bool v0  = (unsigned)cl        < (unsigned)W_;
        const bool v0n = (unsigned)(cl + 1)  < (unsigned)W_;
        const bool v1  = (unsigned)(cl + 32) < (unsigned)W_;
        const bool v1n = (unsigned)(cl + 33) < (unsigned)W_;
        const int y0 = hbase + sh.x;
        const uint2* __restrict__ pr = plane + cl;

        Rw r0 = loadRow(pr, y0,     v0, v0n, v1, v1n);
        Rw r1 = loadRow(pr, y0 + 1, v0, v0n, v1, v1n);
        Rw r2 = loadRow(pr, y0 + 2, v0, v0n, v1, v1n);
        Rw r3 = loadRow(pr, y0 + 3, v0, v0n, v1, v1n);
        Rw r4 = loadRow(pr, y0 + 4, v0, v0n, v1, v1n);

        tap4(acc[0][0], r0.a0, r0.a1, r1.a0, r1.a1, w00, w01, w10, w11);
        tap4(acc[0][1], r0.b0, r0.b1, r1.b0, r1.b1, w00, w01, w10, w11);
        tap4(acc[1][0], r1.a0, r1.a1, r2.a0, r2.a1, w00, w01, w10, w11);
        tap4(acc[1][1], r1.b0, r1.b1, r2.b0, r2.b1, w00, w01, w10, w11);
        tap4(acc[2][0], r2.a0, r2.a1, r3.a0, r3.a1, w00, w01, w10, w11);
        tap4(acc[2][1], r2.b0, r2.b1, r3.b0, r3.b1, w00, w01, w10, w11);
        tap4(acc[3][0], r3.a0, r3.a1, r4.a0, r4.a1, w00, w01, w10, w11);
        tap4(acc[3][1], r3.b0, r3.b1, r4.b0, r4.b1, w00, w01, w10, w11);
    }

    float* __restrict__ ob = out + (size_t)bo * CPO_ * HW_;
    #pragma unroll
    for (int kh = 0; kh < 4; kh++) {
        const int h = hbase + kh;
        #pragma unroll
        for (int g = 0; g < 2; g++) {
            const int w = wpix + g * 32;
            const size_t pix = (size_t)h * W_ + w;
            float c0, c1, c2, c3;
            unpk(acc[kh][g][0], c0, c1);
            unpk(acc[kh][g][1], c2, c3);
            ob[pix]           = c0;
            ob[HW_ + pix]     = c1;
            ob[2 * HW_ + pix] = c2;
            ob[3 * HW_ + pix] = c3;
        }
    }
}

extern "C" void kernel_launch(void* const* d_in, const int* in_sizes, int n_in,
                              void* d_out, int out_size)
{
    const float* x  = (const float*)d_in[0];
    const float* ox = (const float*)d_in[1];
    const float* oy = (const float*)d_in[2];
    const float* ua = (const float*)d_in[3];
    const float* us = (const float*)d_in[4];
    const float* ar = (const float*)d_in[5];
    const float* sr = (const float*)d_in[6];
    float* out = (float*)d_out;

    pre_kernel<<<NT_ + O_/8, 256>>>(x, ox, oy, ua, us, ar, sr);
    disp_kernel<<<dim3(H_ / 16, O_, B_), 256>>>(out);
}

// round 4
// speedup vs baseline: 1.9165x; 1.0674x over previous
#include <cuda_runtime.h>
#include <cuda_fp16.h>

#define B_ 16
#define O_ 32
#define CPO_ 4
#define H_ 128
#define W_ 128
#define S_ 16
#define T_ 32
#define HW_ (H_*W_)
#define NT_ ((B_*O_*H_*W_/4)/256)   /* transpose blocks = 8192 */

typedef unsigned long long ull;

// Scratch: transposed input, (B,O,H,W/2) uint4 = 2 adjacent pixels x 4ch fp16.
__device__ uint4 g_xT4[(size_t)B_ * O_ * H_ * W_ / 2];
__device__ int2  g_shift[O_ * S_];
__device__ uint4 g_wtsh[O_ * S_];   // 4 half2-broadcast weights (W00,W01,W10,W11)

// ---------------------------------------------------------------------------
// packed helpers
// ---------------------------------------------------------------------------
__device__ __forceinline__ void add2(ull& d, ull v) {
    asm("add.rn.f32x2 %0,%0,%1;" : "+l"(d) : "l"(v));
}
__device__ __forceinline__ void unpk(ull v, float& lo, float& hi) {
    asm("mov.b64 {%0,%1},%2;" : "=f"(lo), "=f"(hi) : "l"(v));
}
// half2 bits -> packed float2 in one 64-bit reg (SASS: 2x F2F into a reg pair)
__device__ __forceinline__ ull h2f2(unsigned u) {
    ull r;
    asm("{\n\t.reg .b16 a,b;\n\t.reg .f32 lo,hi;\n\t"
        "mov.b32 {a,b},%1;\n\tcvt.f32.f16 lo,a;\n\tcvt.f32.f16 hi,b;\n\t"
        "mov.b64 %0,{lo,hi};\n\t}" : "=l"(r) : "r"(u));
    return r;
}
__device__ __forceinline__ __half2 u2h(unsigned u) {
    return *reinterpret_cast<__half2*>(&u);
}
__device__ __forceinline__ unsigned h2u(__half2 h) {
    return *reinterpret_cast<unsigned*>(&h);
}

// ---------------------------------------------------------------------------
// Kernel 1 (fused): blocks [0,NT_) transpose, blocks [NT_,NT_+4) params.
// ---------------------------------------------------------------------------
__global__ void pre_kernel(const float* __restrict__ x,
                           const float* __restrict__ ox, const float* __restrict__ oy,
                           const float* __restrict__ ua, const float* __restrict__ us,
                           const float* __restrict__ ar, const float* __restrict__ sr)
{
    if (blockIdx.x < NT_) {
        int idx  = blockIdx.x * 256 + threadIdx.x;      // pixel-group of 4
        int wg   = idx & (W_/4 - 1);
        int rest = idx >> 5;                            // bo*H + h
        size_t base = ((size_t)(rest >> 7) * CPO_ * H_ + (rest & (H_-1))) * W_ + wg * 4;

        float4 c0 = *(const float4*)(x + base);
        float4 c1 = *(const float4*)(x + base + HW_);
        float4 c2 = *(const float4*)(x + base + 2 * HW_);
        float4 c3 = *(const float4*)(x + base + 3 * HW_);

        uint4 o0, o1;
        __half2 h;
        h = __floats2half2_rn(c0.x, c1.x); o0.x = h2u(h);
        h = __floats2half2_rn(c2.x, c3.x); o0.y = h2u(h);
        h = __floats2half2_rn(c0.y, c1.y); o0.z = h2u(h);
        h = __floats2half2_rn(c2.y, c3.y); o0.w = h2u(h);
        h = __floats2half2_rn(c0.z, c1.z); o1.x = h2u(h);
        h = __floats2half2_rn(c2.z, c3.z); o1.y = h2u(h);
        h = __floats2half2_rn(c0.w, c1.w); o1.z = h2u(h);
        h = __floats2half2_rn(c2.w, c3.w); o1.w = h2u(h);

        g_xT4[(size_t)idx * 2]     = o0;
        g_xT4[(size_t)idx * 2 + 1] = o1;
        return;
    }

    // ---- param path ----
    const int lane = threadIdx.x & 31;
    const int o    = (blockIdx.x - NT_) * 8 + (threadIdx.x >> 5);
    const float MINA = 0.024979197860971382f;
    const float PIF  = 3.14159265358979323846f;
    const float EPSF = 1.1920928955078125e-07f;

    float astd = 1.f / (1.f + expf(-ar[o])) * (PIF - MINA) + MINA;
    float sstd = 1.f / (1.f + expf(-sr[o])) * (5.0f - 0.2f) + 0.2f;
    float high_a = fminf(astd * 3.f, PIF);
    float s3 = sstd * 3.f;
    float ia  = 0.5f / (astd * astd + EPSF);
    float isc = 0.5f / (sstd * sstd + EPSF);

    float a = ua[o * T_ + lane] * high_a;
    float s = us[o * T_ + lane] * s3;
    float w = expf(-(a * a * ia + s * s * isc));
    float sum = w;
    #pragma unroll
    for (int d = 16; d; d >>= 1) sum += __shfl_xor_sync(0xffffffffu, sum, d);
    float inv = 2.f / (sum + EPSF);

    if (lane < S_) {
        float oxv = ox[o], oyv = oy[o];
        float dist = sqrtf(oxv * oxv + oyv * oyv);
        float a0 = atan2f(oyv, oxv);

        float ws = w * inv;
        float nd = dist + s;
        float na = a0 + a;
        float dx = nd * cosf(na);
        float dy = nd * sinf(na);
        float fy = floorf(dy), fx = floorf(dx);
        float ay = dy - fy,  axf = dx - fx;
        int iy = max(-H_, min(H_ - 1, (int)fy));
        int ix = max(-W_, min(W_ - 1, (int)fx));
        float wy0 = 1.f - ay, wx0 = 1.f - axf;
        int key = ((iy + 256) << 10) | (ix + 256);

        int rank = 0;
        #pragma unroll
        for (int j = 0; j < S_; j++) {
            int kj = __shfl_sync(0x0000ffffu, key, j);
            rank += (kj < key) || (kj == key && j < lane);
        }
        __half2 h00 = __float2half2_rn(ws * wy0 * wx0);
        __half2 h01 = __float2half2_rn(ws * wy0 * axf);
        __half2 h10 = __float2half2_rn(ws * ay * wx0);
        __half2 h11 = __float2half2_rn(ws * ay * axf);
        g_shift[o * S_ + rank] = make_int2(iy, ix);
        g_wtsh[o * S_ + rank]  = make_uint4(h2u(h00), h2u(h01), h2u(h10), h2u(h11));
    }
}

// ---------------------------------------------------------------------------
// Kernel 2: main gather.
// Block = 256 = 8 warps. Warp = 32 lanes x 2 ADJACENT pixels (wp=2*lane+64*half),
// 4 row-groups x KH=4 rows. Per sample: 5 rows x 2 predicated LDG.128.
// Taps in HFMA2, parity resolved by block-uniform template branch.
// fp16 accumulates a sample PAIR, flushed to packed fp32x2 every 2 samples.
// ---------------------------------------------------------------------------
template<bool ODD, bool FIRST>
__device__ __forceinline__ void do_taps(const uint4 Q[5][2], uint2 hacc[4][2],
                                        __half2 w00, __half2 w01, __half2 w10, __half2 w11)
{
    #pragma unroll
    for (int kh = 0; kh < 4; kh++) {
        const uint4& T0 = Q[kh][0];     const uint4& T1 = Q[kh][1];
        const uint4& U0 = Q[kh + 1][0]; const uint4& U1 = Q[kh + 1][1];
        // col slots S0,S1,S2: each {ch01, ch23}
        unsigned ta0 = ODD ? T0.z : T0.x, ta1 = ODD ? T0.w : T0.y;
        unsigned tb0 = ODD ? T1.x : T0.z, tb1 = ODD ? T1.y : T0.w;
        unsigned tc0 = ODD ? T1.z : T1.x, tc1 = ODD ? T1.w : T1.y;
        unsigned ua0 = ODD ? U0.z : U0.x, ua1 = ODD ? U0.w : U0.y;
        unsigned ub0 = ODD ? U1.x : U0.z, ub1 = ODD ? U1.y : U0.w;
        unsigned uc0 = ODD ? U1.z : U1.x, uc1 = ODD ? U1.w : U1.y;

        __half2 a;
        // pixel0 ch01
        a = FIRST ? __hmul2(u2h(ta0), w00) : __hfma2(u2h(ta0), w00, u2h(hacc[kh][0].x));
        a = __hfma2(u2h(tb0), w01, a);
        a = __hfma2(u2h(ua0), w10, a);
        a = __hfma2(u2h(ub0), w11, a);
        hacc[kh][0].x = h2u(a);
        // pixel0 ch23
        a = FIRST ? __hmul2(u2h(ta1), w00) : __hfma2(u2h(ta1), w00, u2h(hacc[kh][0].y));
        a = __hfma2(u2h(tb1), w01, a);
        a = __hfma2(u2h(ua1), w10, a);
        a = __hfma2(u2h(ub1), w11, a);
        hacc[kh][0].y = h2u(a);
        // pixel1 ch01
        a = FIRST ? __hmul2(u2h(tb0), w00) : __hfma2(u2h(tb0), w00, u2h(hacc[kh][1].x));
        a = __hfma2(u2h(tc0), w01, a);
        a = __hfma2(u2h(ub0), w10, a);
        a = __hfma2(u2h(uc0), w11, a);
        hacc[kh][1].x = h2u(a);
        // pixel1 ch23
        a = FIRST ? __hmul2(u2h(tb1), w00) : __hfma2(u2h(tb1), w00, u2h(hacc[kh][1].y));
        a = __hfma2(u2h(tc1), w01, a);
        a = __hfma2(u2h(ub1), w10, a);
        a = __hfma2(u2h(uc1), w11, a);
        hacc[kh][1].y = h2u(a);
    }
}

template<bool FIRST>
__device__ __forceinline__ void do_sample(int s, const int2* s_sh, const uint4* s_w,
                                          int wp, int hbase,
                                          const uint4* __restrict__ plane,
                                          uint2 hacc[4][2])
{
    const int2  sh = s_sh[s];
    const uint4 wv = s_w[s];
    const __half2 w00 = u2h(wv.x), w01 = u2h(wv.y), w10 = u2h(wv.z), w11 = u2h(wv.w);
    const int cl = wp + sh.y;
    const int eb = cl & ~1;
    const bool odd = (sh.y & 1);
    const int y0 = hbase + sh.x;
    const bool q0v = (unsigned)eb       < (unsigned)W_;
    const bool q1v = (unsigned)(eb + 2) < (unsigned)W_;
    const uint4* __restrict__ pb = plane + (eb >> 1);

    uint4 Q[5][2];
    #pragma unroll
    for (int r = 0; r < 5; r++) {
        int y = y0 + r;
        bool yv = (unsigned)y < (unsigned)H_;
        const uint4* p = pb + y * (W_ / 2);
        uint4 z = make_uint4(0u, 0u, 0u, 0u);
        Q[r][0] = z; Q[r][1] = z;
        if (q0v && yv) Q[r][0] = p[0];
        if (q1v && yv) Q[r][1] = p[1];
    }
    if (odd) do_taps<true,  FIRST>(Q, hacc, w00, w01, w10, w11);
    else     do_taps<false, FIRST>(Q, hacc, w00, w01, w10, w11);
}

__global__ void __launch_bounds__(256, 2) disp_kernel(float* __restrict__ out)
{
    __shared__ int2  s_sh[S_];
    __shared__ uint4 s_w[S_];
    const int tid = threadIdx.x;
    const int o = blockIdx.y, b = blockIdx.z;
    const int bo = b * O_ + o;
    if (tid < S_) { s_sh[tid] = g_shift[o * S_ + tid]; s_w[tid] = g_wtsh[o * S_ + tid]; }
    __syncthreads();

    const int lane = tid & 31, warp = tid >> 5;
    const int half = warp & 1, hy = warp >> 1;
    const int hbase = blockIdx.x * 16 + hy * 4;
    const int wp = half * 64 + lane * 2;
    const uint4* __restrict__ plane = g_xT4 + (size_t)bo * (HW_ / 2);

    ull facc[4][2][2];
    #pragma unroll
    for (int i = 0; i < 4; i++)
        #pragma unroll
        for (int g = 0; g < 2; g++) { facc[i][g][0] = 0ull; facc[i][g][1] = 0ull; }

    #pragma unroll 1
    for (int sp = 0; sp < S_; sp += 2) {
        uint2 hacc[4][2];
        do_sample<true >(sp,     s_sh, s_w, wp, hbase, plane, hacc);
        do_sample<false>(sp + 1, s_sh, s_w, wp, hbase, plane, hacc);
        #pragma unroll
        for (int kh = 0; kh < 4; kh++)
            #pragma unroll
            for (int g = 0; g < 2; g++) {
                add2(facc[kh][g][0], h2f2(hacc[kh][g].x));
                add2(facc[kh][g][1], h2f2(hacc[kh][g].y));
            }
    }

    float* __restrict__ ob = out + (size_t)bo * CPO_ * HW_;
    #pragma unroll
    for (int kh = 0; kh < 4; kh++) {
        const int h = hbase + kh;
        float p0[4], p1[4];
        unpk(facc[kh][0][0], p0[0], p0[1]);
        unpk(facc[kh][0][1], p0[2], p0[3]);
        unpk(facc[kh][1][0], p1[0], p1[1]);
        unpk(facc[kh][1][1], p1[2], p1[3]);
        #pragma unroll
        for (int c = 0; c < 4; c++) {
            float2 v = make_float2(p0[c], p1[c]);
            *reinterpret_cast<float2*>(ob + (size_t)c * HW_ + (size_t)h * W_ + wp) = v;
        }
    }
}

extern "C" void kernel_launch(void* const* d_in, const int* in_sizes, int n_in,
                              void* d_out, int out_size)
{
    const float* x  = (const float*)d_in[0];
    const float* ox = (const float*)d_in[1];
    const float* oy = (const float*)d_in[2];
    const float* ua = (const float*)d_in[3];
    const float* us = (const float*)d_in[4];
    const float* ar = (const float*)d_in[5];
    const float* sr = (const float*)d_in[6];
    float* out = (float*)d_out;

    pre_kernel<<<NT_ + O_/8, 256>>>(x, ox, oy, ua, us, ar, sr);
    disp_kernel<<<dim3(H_ / 16, O_, B_), 256>>>(out);
}

// round 5
// speedup vs baseline: 2.0612x; 1.0755x over previous
#include <cuda_runtime.h>
#include <cuda_fp16.h>

#define B_ 16
#define O_ 32
#define CPO_ 4
#define H_ 128
#define W_ 128
#define S_ 16
#define T_ 32
#define HW_ (H_*W_)
#define NT_ ((B_*O_*H_*W_/4)/256)   /* transpose blocks = 8192 */

typedef unsigned long long ull;

// Scratch: transposed input, (B,O,H,W/2) uint4 = 2 adjacent pixels x 4ch fp16.
__device__ uint4 g_xT4[(size_t)B_ * O_ * H_ * W_ / 2];
__device__ int2  g_shift[O_ * S_];
__device__ uint4 g_wtsh[O_ * S_];
// Zero page: out-of-bounds loads are redirected here (covers offsets r*64+1).
__device__ uint4 g_zero[4 * 64 + 8];   // zero-initialized by definition

// ---------------------------------------------------------------------------
// packed helpers
// ---------------------------------------------------------------------------
__device__ __forceinline__ void add2(ull& d, ull v) {
    asm("add.rn.f32x2 %0,%0,%1;" : "+l"(d) : "l"(v));
}
__device__ __forceinline__ void unpk(ull v, float& lo, float& hi) {
    asm("mov.b64 {%0,%1},%2;" : "=f"(lo), "=f"(hi) : "l"(v));
}
__device__ __forceinline__ ull h2f2(unsigned u) {
    ull r;
    asm("{\n\t.reg .b16 a,b;\n\t.reg .f32 lo,hi;\n\t"
        "mov.b32 {a,b},%1;\n\tcvt.f32.f16 lo,a;\n\tcvt.f32.f16 hi,b;\n\t"
        "mov.b64 %0,{lo,hi};\n\t}" : "=l"(r) : "r"(u));
    return r;
}
__device__ __forceinline__ __half2 u2h(unsigned u) {
    return *reinterpret_cast<__half2*>(&u);
}
__device__ __forceinline__ unsigned h2u(__half2 h) {
    return *reinterpret_cast<unsigned*>(&h);
}

// ---------------------------------------------------------------------------
// Kernel 1 (fused): blocks [0,NT_) transpose, blocks [NT_,NT_+4) params.
// ---------------------------------------------------------------------------
__global__ void pre_kernel(const float* __restrict__ x,
                           const float* __restrict__ ox, const float* __restrict__ oy,
                           const float* __restrict__ ua, const float* __restrict__ us,
                           const float* __restrict__ ar, const float* __restrict__ sr)
{
    if (blockIdx.x < NT_) {
        int idx  = blockIdx.x * 256 + threadIdx.x;      // pixel-group of 4
        int wg   = idx & (W_/4 - 1);
        int rest = idx >> 5;                            // bo*H + h
        size_t base = ((size_t)(rest >> 7) * CPO_ * H_ + (rest & (H_-1))) * W_ + wg * 4;

        float4 c0 = *(const float4*)(x + base);
        float4 c1 = *(const float4*)(x + base + HW_);
        float4 c2 = *(const float4*)(x + base + 2 * HW_);
        float4 c3 = *(const float4*)(x + base + 3 * HW_);

        uint4 o0, o1;
        __half2 h;
        h = __floats2half2_rn(c0.x, c1.x); o0.x = h2u(h);
        h = __floats2half2_rn(c2.x, c3.x); o0.y = h2u(h);
        h = __floats2half2_rn(c0.y, c1.y); o0.z = h2u(h);
        h = __floats2half2_rn(c2.y, c3.y); o0.w = h2u(h);
        h = __floats2half2_rn(c0.z, c1.z); o1.x = h2u(h);
        h = __floats2half2_rn(c2.z, c3.z); o1.y = h2u(h);
        h = __floats2half2_rn(c0.w, c1.w); o1.z = h2u(h);
        h = __floats2half2_rn(c2.w, c3.w); o1.w = h2u(h);

        g_xT4[(size_t)idx * 2]     = o0;
        g_xT4[(size_t)idx * 2 + 1] = o1;
        return;
    }

    // ---- param path ----
    const int lane = threadIdx.x & 31;
    const int o    = (blockIdx.x - NT_) * 8 + (threadIdx.x >> 5);
    const float MINA = 0.024979197860971382f;
    const float PIF  = 3.14159265358979323846f;
    const float EPSF = 1.1920928955078125e-07f;

    float astd = 1.f / (1.f + expf(-ar[o])) * (PIF - MINA) + MINA;
    float sstd = 1.f / (1.f + expf(-sr[o])) * (5.0f - 0.2f) + 0.2f;
    float high_a = fminf(astd * 3.f, PIF);
    float s3 = sstd * 3.f;
    float ia  = 0.5f / (astd * astd + EPSF);
    float isc = 0.5f / (sstd * sstd + EPSF);

    float a = ua[o * T_ + lane] * high_a;
    float s = us[o * T_ + lane] * s3;
    float w = expf(-(a * a * ia + s * s * isc));
    float sum = w;
    #pragma unroll
    for (int d = 16; d; d >>= 1) sum += __shfl_xor_sync(0xffffffffu, sum, d);
    float inv = 2.f / (sum + EPSF);

    if (lane < S_) {
        float oxv = ox[o], oyv = oy[o];
        float dist = sqrtf(oxv * oxv + oyv * oyv);
        float a0 = atan2f(oyv, oxv);

        float ws = w * inv;
        float nd = dist + s;
        float na = a0 + a;
        float dx = nd * cosf(na);
        float dy = nd * sinf(na);
        float fy = floorf(dy), fx = floorf(dx);
        float ay = dy - fy,  axf = dx - fx;
        int iy = max(-H_, min(H_ - 1, (int)fy));
        int ix = max(-W_, min(W_ - 1, (int)fx));
        float wy0 = 1.f - ay, wx0 = 1.f - axf;
        int key = ((iy + 256) << 10) | (ix + 256);

        int rank = 0;
        #pragma unroll
        for (int j = 0; j < S_; j++) {
            int kj = __shfl_sync(0x0000ffffu, key, j);
            rank += (kj < key) || (kj == key && j < lane);
        }
        __half2 h00 = __float2half2_rn(ws * wy0 * wx0);
        __half2 h01 = __float2half2_rn(ws * wy0 * axf);
        __half2 h10 = __float2half2_rn(ws * ay * wx0);
        __half2 h11 = __float2half2_rn(ws * ay * axf);
        g_shift[o * S_ + rank] = make_int2(iy, ix);
        g_wtsh[o * S_ + rank]  = make_uint4(h2u(h00), h2u(h01), h2u(h10), h2u(h11));
    }
}

// ---------------------------------------------------------------------------
// Kernel 2: main gather.
// Warp = 32 lanes x 2 adjacent pixels; 4 row-groups x KH=4 rows.
// Per sample: 10 UNCONDITIONAL LDG.128 at [selected_base + imm]; OOB columns
// and OOB rows redirect the base pointer to a zero page (no predicated loads,
// no zero-fill movs). Row validity resolved by a warp-uniform fast path.
// fp16 accumulates 4 samples, flushed to packed fp32x2 once per group.
// ---------------------------------------------------------------------------
template<bool ODD, bool FIRST>
__device__ __forceinline__ void do_taps(const uint4 Q[5][2], uint2 hacc[4][2],
                                        __half2 w00, __half2 w01, __half2 w10, __half2 w11)
{
    #pragma unroll
    for (int kh = 0; kh < 4; kh++) {
        const uint4& T0 = Q[kh][0];     const uint4& T1 = Q[kh][1];
        const uint4& U0 = Q[kh + 1][0]; const uint4& U1 = Q[kh + 1][1];
        unsigned ta0 = ODD ? T0.z : T0.x, ta1 = ODD ? T0.w : T0.y;
        unsigned tb0 = ODD ? T1.x : T0.z, tb1 = ODD ? T1.y : T0.w;
        unsigned tc0 = ODD ? T1.z : T1.x, tc1 = ODD ? T1.w : T1.y;
        unsigned ua0 = ODD ? U0.z : U0.x, ua1 = ODD ? U0.w : U0.y;
        unsigned ub0 = ODD ? U1.x : U0.z, ub1 = ODD ? U1.y : U0.w;
        unsigned uc0 = ODD ? U1.z : U1.x, uc1 = ODD ? U1.w : U1.y;

        __half2 a;
        a = FIRST ? __hmul2(u2h(ta0), w00) : __hfma2(u2h(ta0), w00, u2h(hacc[kh][0].x));
        a = __hfma2(u2h(tb0), w01, a);
        a = __hfma2(u2h(ua0), w10, a);
        a = __hfma2(u2h(ub0), w11, a);
        hacc[kh][0].x = h2u(a);
        a = FIRST ? __hmul2(u2h(ta1), w00) : __hfma2(u2h(ta1), w00, u2h(hacc[kh][0].y));
        a = __hfma2(u2h(tb1), w01, a);
        a = __hfma2(u2h(ua1), w10, a);
        a = __hfma2(u2h(ub1), w11, a);
        hacc[kh][0].y = h2u(a);
        a = FIRST ? __hmul2(u2h(tb0), w00) : __hfma2(u2h(tb0), w00, u2h(hacc[kh][1].x));
        a = __hfma2(u2h(tc0), w01, a);
        a = __hfma2(u2h(ub0), w10, a);
        a = __hfma2(u2h(uc0), w11, a);
        hacc[kh][1].x = h2u(a);
        a = FIRST ? __hmul2(u2h(tb1), w00) : __hfma2(u2h(tb1), w00, u2h(hacc[kh][1].y));
        a = __hfma2(u2h(tc1), w01, a);
        a = __hfma2(u2h(ub1), w10, a);
        a = __hfma2(u2h(uc1), w11, a);
        hacc[kh][1].y = h2u(a);
    }
}

template<bool FIRST>
__device__ __forceinline__ void do_sample(int s, const int2* s_sh, const uint4* s_w,
                                          int wp, int hbase,
                                          const uint4* __restrict__ plane,
                                          uint2 hacc[4][2])
{
    const int2  sh = s_sh[s];
    const uint4 wv = s_w[s];
    const __half2 w00 = u2h(wv.x), w01 = u2h(wv.y), w10 = u2h(wv.z), w11 = u2h(wv.w);
    const int eb  = (wp + sh.y) & ~1;
    const int ebh = eb >> 1;
    const int y0  = hbase + sh.x;
    const bool q0 = (unsigned)eb       < (unsigned)W_;
    const bool q1 = (unsigned)(eb + 2) < (unsigned)W_;
    const uint4* __restrict__ zp = g_zero;

    uint4 Q[5][2];
    if (y0 >= 0 && y0 <= H_ - 5) {            // warp-uniform fast path
        const uint4* __restrict__ pA = q0 ? plane + y0 * (W_/2) + ebh     : zp;
        const uint4* __restrict__ pB = q1 ? plane + y0 * (W_/2) + ebh + 1 : zp;
        #pragma unroll
        for (int r = 0; r < 5; r++) {
            Q[r][0] = pA[r * (W_/2)];
            Q[r][1] = pB[r * (W_/2)];
        }
    } else {                                   // edge windows: per-row select
        #pragma unroll
        for (int r = 0; r < 5; r++) {
            int y = y0 + r;
            bool yv = (unsigned)y < (unsigned)H_;
            const uint4* pA = (q0 && yv) ? plane + y * (W_/2) + ebh     : zp;
            const uint4* pB = (q1 && yv) ? plane + y * (W_/2) + ebh + 1 : zp;
            Q[r][0] = pA[0];
            Q[r][1] = pB[0];
        }
    }

    if (sh.y & 1) do_taps<true,  FIRST>(Q, hacc, w00, w01, w10, w11);
    else          do_taps<false, FIRST>(Q, hacc, w00, w01, w10, w11);
}

__global__ void __launch_bounds__(256, 2) disp_kernel(float* __restrict__ out)
{
    __shared__ int2  s_sh[S_];
    __shared__ uint4 s_w[S_];
    const int tid = threadIdx.x;
    const int o = blockIdx.y, b = blockIdx.z;
    const int bo = b * O_ + o;
    if (tid < S_) { s_sh[tid] = g_shift[o * S_ + tid]; s_w[tid] = g_wtsh[o * S_ + tid]; }
    __syncthreads();

    const int lane = tid & 31, warp = tid >> 5;
    const int half = warp & 1, hy = warp >> 1;
    const int hbase = blockIdx.x * 16 + hy * 4;
    const int wp = half * 64 + lane * 2;
    const uint4* __restrict__ plane = g_xT4 + (size_t)bo * (HW_ / 2);

    ull facc[4][2][2];
    #pragma unroll
    for (int i = 0; i < 4; i++)
        #pragma unroll
        for (int g = 0; g < 2; g++) { facc[i][g][0] = 0ull; facc[i][g][1] = 0ull; }

    #pragma unroll 1
    for (int sp = 0; sp < S_; sp += 4) {
        uint2 hacc[4][2];
        do_sample<true >(sp,     s_sh, s_w, wp, hbase, plane, hacc);
        do_sample<false>(sp + 1, s_sh, s_w, wp, hbase, plane, hacc);
        do_sample<false>(sp + 2, s_sh, s_w, wp, hbase, plane, hacc);
        do_sample<false>(sp + 3, s_sh, s_w, wp, hbase, plane, hacc);
        #pragma unroll
        for (int kh = 0; kh < 4; kh++)
            #pragma unroll
            for (int g = 0; g < 2; g++) {
                add2(facc[kh][g][0], h2f2(hacc[kh][g].x));
                add2(facc[kh][g][1], h2f2(hacc[kh][g].y));
            }
    }

    float* __restrict__ ob = out + (size_t)bo * CPO_ * HW_;
    #pragma unroll
    for (int kh = 0; kh < 4; kh++) {
        const int h = hbase + kh;
        float p0[4], p1[4];
        unpk(facc[kh][0][0], p0[0], p0[1]);
        unpk(facc[kh][0][1], p0[2], p0[3]);
        unpk(facc[kh][1][0], p1[0], p1[1]);
        unpk(facc[kh][1][1], p1[2], p1[3]);
        #pragma unroll
        for (int c = 0; c < 4; c++) {
            float2 v = make_float2(p0[c], p1[c]);
            *reinterpret_cast<float2*>(ob + (size_t)c * HW_ + (size_t)h * W_ + wp) = v;
        }
    }
}

extern "C" void kernel_launch(void* const* d_in, const int* in_sizes, int n_in,
                              void* d_out, int out_size)
{
    const float* x  = (const float*)d_in[0];
    const float* ox = (const float*)d_in[1];
    const float* oy = (const float*)d_in[2];
    const float* ua = (const float*)d_in[3];
    const float* us = (const float*)d_in[4];
    const float* ar = (const float*)d_in[5];
    const float* sr = (const float*)d_in[6];
    float* out = (float*)d_out;

    pre_kernel<<<NT_ + O_/8, 256>>>(x, ox, oy, ua, us, ar, sr);
    disp_kernel<<<dim3(H_ / 16, O_, B_), 256>>>(out);
}

// round 6
// speedup vs baseline: 2.1279x; 1.0324x over previous
#include <cuda_runtime.h>
#include <cuda_fp16.h>

#define B_ 16
#define O_ 32
#define CPO_ 4
#define H_ 128
#define W_ 128
#define S_ 16
#define T_ 32
#define HW_ (H_*W_)
#define NT_ ((B_*O_*H_*W_/4)/256)   /* transpose blocks = 8192 */
#define ROWB_ (W_/2*16)             /* bytes per scratch row = 1024 */

typedef unsigned long long ull;

// Scratch: transposed input, (B,O,H,W/2) uint4 = 2 adjacent pixels x 4ch fp16.
__device__ uint4 g_xT4[(size_t)B_ * O_ * H_ * W_ / 2];
__device__ int2  g_shift[O_ * S_];
__device__ uint4 g_wtsh[O_ * S_];
// Zero page: out-of-bounds loads redirect here (row stride up to 4*1024B + 16).
__device__ uint4 g_zero[4 * 64 + 8];   // zero-initialized by definition

// ---------------------------------------------------------------------------
// packed helpers
// ---------------------------------------------------------------------------
__device__ __forceinline__ void add2(ull& d, ull v) {
    asm("add.rn.f32x2 %0,%0,%1;" : "+l"(d) : "l"(v));
}
__device__ __forceinline__ void unpk(ull v, float& lo, float& hi) {
    asm("mov.b64 {%0,%1},%2;" : "=f"(lo), "=f"(hi) : "l"(v));
}
__device__ __forceinline__ ull h2f2(unsigned u) {
    ull r;
    asm("{\n\t.reg .b16 a,b;\n\t.reg .f32 lo,hi;\n\t"
        "mov.b32 {a,b},%1;\n\tcvt.f32.f16 lo,a;\n\tcvt.f32.f16 hi,b;\n\t"
        "mov.b64 %0,{lo,hi};\n\t}" : "=l"(r) : "r"(u));
    return r;
}
__device__ __forceinline__ __half2 u2h(unsigned u) {
    return *reinterpret_cast<__half2*>(&u);
}
__device__ __forceinline__ unsigned h2u(__half2 h) {
    return *reinterpret_cast<unsigned*>(&h);
}

// ---------------------------------------------------------------------------
// Kernel 1 (fused): blocks [0,NT_) transpose, blocks [NT_,NT_+4) params.
// ---------------------------------------------------------------------------
__global__ void pre_kernel(const float* __restrict__ x,
                           const float* __restrict__ ox, const float* __restrict__ oy,
                           const float* __restrict__ ua, const float* __restrict__ us,
                           const float* __restrict__ ar, const float* __restrict__ sr)
{
    if (blockIdx.x < NT_) {
        int idx  = blockIdx.x * 256 + threadIdx.x;      // pixel-group of 4
        int wg   = idx & (W_/4 - 1);
        int rest = idx >> 5;                            // bo*H + h
        size_t base = ((size_t)(rest >> 7) * CPO_ * H_ + (rest & (H_-1))) * W_ + wg * 4;

        float4 c0 = *(const float4*)(x + base);
        float4 c1 = *(const float4*)(x + base + HW_);
        float4 c2 = *(const float4*)(x + base + 2 * HW_);
        float4 c3 = *(const float4*)(x + base + 3 * HW_);

        uint4 o0, o1;
        __half2 h;
        h = __floats2half2_rn(c0.x, c1.x); o0.x = h2u(h);
        h = __floats2half2_rn(c2.x, c3.x); o0.y = h2u(h);
        h = __floats2half2_rn(c0.y, c1.y); o0.z = h2u(h);
        h = __floats2half2_rn(c2.y, c3.y); o0.w = h2u(h);
        h = __floats2half2_rn(c0.z, c1.z); o1.x = h2u(h);
        h = __floats2half2_rn(c2.z, c3.z); o1.y = h2u(h);
        h = __floats2half2_rn(c0.w, c1.w); o1.z = h2u(h);
        h = __floats2half2_rn(c2.w, c3.w); o1.w = h2u(h);

        g_xT4[(size_t)idx * 2]     = o0;
        g_xT4[(size_t)idx * 2 + 1] = o1;
        return;
    }

    // ---- param path ----
    const int lane = threadIdx.x & 31;
    const int o    = (blockIdx.x - NT_) * 8 + (threadIdx.x >> 5);
    const float MINA = 0.024979197860971382f;
    const float PIF  = 3.14159265358979323846f;
    const float EPSF = 1.1920928955078125e-07f;

    float astd = 1.f / (1.f + expf(-ar[o])) * (PIF - MINA) + MINA;
    float sstd = 1.f / (1.f + expf(-sr[o])) * (5.0f - 0.2f) + 0.2f;
    float high_a = fminf(astd * 3.f, PIF);
    float s3 = sstd * 3.f;
    float ia  = 0.5f / (astd * astd + EPSF);
    float isc = 0.5f / (sstd * sstd + EPSF);

    float a = ua[o * T_ + lane] * high_a;
    float s = us[o * T_ + lane] * s3;
    float w = expf(-(a * a * ia + s * s * isc));
    float sum = w;
    #pragma unroll
    for (int d = 16; d; d >>= 1) sum += __shfl_xor_sync(0xffffffffu, sum, d);
    float inv = 2.f / (sum + EPSF);

    if (lane < S_) {
        float oxv = ox[o], oyv = oy[o];
        float dist = sqrtf(oxv * oxv + oyv * oyv);
        float a0 = atan2f(oyv, oxv);

        float ws = w * inv;
        float nd = dist + s;
        float na = a0 + a;
        float dx = nd * cosf(na);
        float dy = nd * sinf(na);
        float fy = floorf(dy), fx = floorf(dx);
        float ay = dy - fy,  axf = dx - fx;
        int iy = max(-H_, min(H_ - 1, (int)fy));
        int ix = max(-W_, min(W_ - 1, (int)fx));
        float wy0 = 1.f - ay, wx0 = 1.f - axf;
        int key = ((iy + 256) << 10) | (ix + 256);

        int rank = 0;
        #pragma unroll
        for (int j = 0; j < S_; j++) {
            int kj = __shfl_sync(0x0000ffffu, key, j);
            rank += (kj < key) || (kj == key && j < lane);
        }
        __half2 h00 = __float2half2_rn(ws * wy0 * wx0);
        __half2 h01 = __float2half2_rn(ws * wy0 * axf);
        __half2 h10 = __float2half2_rn(ws * ay * wx0);
        __half2 h11 = __float2half2_rn(ws * ay * axf);
        g_shift[o * S_ + rank] = make_int2(iy, ix);
        g_wtsh[o * S_ + rank]  = make_uint4(h2u(h00), h2u(h01), h2u(h10), h2u(h11));
    }
}

// ---------------------------------------------------------------------------
// Kernel 2: main gather.
// Warp = 32 lanes x 2 adjacent pixels; 4 row-groups x KH=4 rows.
// Per sample-row: 1 LDG.128 + 1 LDG.64 (6 L1 wavefronts, the exact 3 column
// slots the taps consume). OOB columns/rows redirect base pointers to a zero
// page. Taps in HFMA2; fp16 accumulates 4 samples then flushes to fp32x2.
// ---------------------------------------------------------------------------
struct Row6 { unsigned a0, a1, b0, b1, c0, c1; };

template<bool FIRST>
__device__ __forceinline__ void do_taps(const Row6 R[5], uint2 hacc[4][2],
                                        __half2 w00, __half2 w01, __half2 w10, __half2 w11)
{
    #pragma unroll
    for (int kh = 0; kh < 4; kh++) {
        const Row6& Tr = R[kh];
        const Row6& Ur = R[kh + 1];
        __half2 a;
        // pixel0 ch01
        a = FIRST ? __hmul2(u2h(Tr.a0), w00) : __hfma2(u2h(Tr.a0), w00, u2h(hacc[kh][0].x));
        a = __hfma2(u2h(Tr.b0), w01, a);
        a = __hfma2(u2h(Ur.a0), w10, a);
        a = __hfma2(u2h(Ur.b0), w11, a);
        hacc[kh][0].x = h2u(a);
        // pixel0 ch23
        a = FIRST ? __hmul2(u2h(Tr.a1), w00) : __hfma2(u2h(Tr.a1), w00, u2h(hacc[kh][0].y));
        a = __hfma2(u2h(Tr.b1), w01, a);
        a = __hfma2(u2h(Ur.a1), w10, a);
        a = __hfma2(u2h(Ur.b1), w11, a);
        hacc[kh][0].y = h2u(a);
        // pixel1 ch01
        a = FIRST ? __hmul2(u2h(Tr.b0), w00) : __hfma2(u2h(Tr.b0), w00, u2h(hacc[kh][1].x));
        a = __hfma2(u2h(Tr.c0), w01, a);
        a = __hfma2(u2h(Ur.b0), w10, a);
        a = __hfma2(u2h(Ur.c0), w11, a);
        hacc[kh][1].x = h2u(a);
        // pixel1 ch23
        a = FIRST ? __hmul2(u2h(Tr.b1), w00) : __hfma2(u2h(Tr.b1), w00, u2h(hacc[kh][1].y));
        a = __hfma2(u2h(Tr.c1), w01, a);
        a = __hfma2(u2h(Ur.b1), w10, a);
        a = __hfma2(u2h(Ur.c1), w11, a);
        hacc[kh][1].y = h2u(a);
    }
}

template<bool ODD>
__device__ __forceinline__ Row6 mapRow(uint4 A, uint2 Bv)
{
    Row6 r;
    if (ODD) { r.a0 = Bv.x; r.a1 = Bv.y; r.b0 = A.x; r.b1 = A.y; r.c0 = A.z; r.c1 = A.w; }
    else     { r.a0 = A.x;  r.a1 = A.y;  r.b0 = A.z; r.b1 = A.w; r.c0 = Bv.x; r.c1 = Bv.y; }
    return r;
}

template<bool ODD, bool FIRST>
__device__ __forceinline__ void do_sample_t(int2 sh, uint4 wv,
                                            int wp, int hbase,
                                            const char* __restrict__ planeB,
                                            uint2 hacc[4][2])
{
    const __half2 w00 = u2h(wv.x), w01 = u2h(wv.y), w10 = u2h(wv.z), w11 = u2h(wv.w);
    const int eb = (wp + sh.y) & ~1;
    const int y0 = hbase + sh.x;
    const bool q0 = (unsigned)eb       < (unsigned)W_;
    const bool q1 = (unsigned)(eb + 2) < (unsigned)W_;
    const char* __restrict__ zp = (const char*)g_zero;
    // base of block ebh within a row
    const char* cb = planeB + eb * 8;               // (eb/2)*16
    const bool  q4 = ODD ? q1 : q0;
    const bool  q2 = ODD ? q0 : q1;
    const int   o4 = ODD ? 16 : 0;
    const int   o2 = ODD ? 8  : 16;

    Row6 R[5];
    if (y0 >= 0 && y0 <= H_ - 5) {                  // warp-uniform fast path
        const char* p4 = q4 ? cb + y0 * ROWB_ + o4 : zp;
        const char* p2 = q2 ? cb + y0 * ROWB_ + o2 : zp;
        #pragma unroll
        for (int r = 0; r < 5; r++) {
            uint4 A  = *(const uint4*)(p4 + r * ROWB_);
            uint2 Bv = *(const uint2*)(p2 + r * ROWB_);
            R[r] = mapRow<ODD>(A, Bv);
        }
    } else {                                         // edge windows
        #pragma unroll
        for (int r = 0; r < 5; r++) {
            int y = y0 + r;
            bool yv = (unsigned)y < (unsigned)H_;
            const char* p4 = (q4 && yv) ? cb + y * ROWB_ + o4 : zp;
            const char* p2 = (q2 && yv) ? cb + y * ROWB_ + o2 : zp;
            uint4 A  = *(const uint4*)p4;
            uint2 Bv = *(const uint2*)p2;
            R[r] = mapRow<ODD>(A, Bv);
        }
    }
    do_taps<FIRST>(R, hacc, w00, w01, w10, w11);
}

template<bool FIRST>
__device__ __forceinline__ void do_sample(int s, const int2* s_sh, const uint4* s_w,
                                          int wp, int hbase,
                                          const char* __restrict__ planeB,
                                          uint2 hacc[4][2])
{
    const int2  sh = s_sh[s];
    const uint4 wv = s_w[s];
    if (sh.y & 1) do_sample_t<true,  FIRST>(sh, wv, wp, hbase, planeB, hacc);
    else          do_sample_t<false, FIRST>(sh, wv, wp, hbase, planeB, hacc);
}

__global__ void __launch_bounds__(256, 2) disp_kernel(float* __restrict__ out)
{
    __shared__ int2  s_sh[S_];
    __shared__ uint4 s_w[S_];
    const int tid = threadIdx.x;
    const int o = blockIdx.y, b = blockIdx.z;
    const int bo = b * O_ + o;
    if (tid < S_) { s_sh[tid] = g_shift[o * S_ + tid]; s_w[tid] = g_wtsh[o * S_ + tid]; }
    __syncthreads();

    const int lane = tid & 31, warp = tid >> 5;
    const int half = warp & 1, hy = warp >> 1;
    const int hbase = blockIdx.x * 16 + hy * 4;
    const int wp = half * 64 + lane * 2;
    const char* __restrict__ planeB =
        (const char*)(g_xT4 + (size_t)bo * (HW_ / 2));

    ull facc[4][2][2];
    #pragma unroll
    for (int i = 0; i < 4; i++)
        #pragma unroll
        for (int g = 0; g < 2; g++) { facc[i][g][0] = 0ull; facc[i][g][1] = 0ull; }

    #pragma unroll 1
    for (int sp = 0; sp < S_; sp += 4) {
        uint2 hacc[4][2];
        do_sample<true >(sp,     s_sh, s_w, wp, hbase, planeB, hacc);
        do_sample<false>(sp + 1, s_sh, s_w, wp, hbase, planeB, hacc);
        do_sample<false>(sp + 2, s_sh, s_w, wp, hbase, planeB, hacc);
        do_sample<false>(sp + 3, s_sh, s_w, wp, hbase, planeB, hacc);
        #pragma unroll
        for (int kh = 0; kh < 4; kh++)
            #pragma unroll
            for (int g = 0; g < 2; g++) {
                add2(facc[kh][g][0], h2f2(hacc[kh][g].x));
                add2(facc[kh][g][1], h2f2(hacc[kh][g].y));
            }
    }

    float* __restrict__ ob = out + (size_t)bo * CPO_ * HW_;
    #pragma unroll
    for (int kh = 0; kh < 4; kh++) {
        const int h = hbase + kh;
        float p0[4], p1[4];
        unpk(facc[kh][0][0], p0[0], p0[1]);
        unpk(facc[kh][0][1], p0[2], p0[3]);
        unpk(facc[kh][1][0], p1[0], p1[1]);
        unpk(facc[kh][1][1], p1[2], p1[3]);
        #pragma unroll
        for (int c = 0; c < 4; c++) {
            float2 v = make_float2(p0[c], p1[c]);
            *reinterpret_cast<float2*>(ob + (size_t)c * HW_ + (size_t)h * W_ + wp) = v;
        }
    }
}

extern "C" void kernel_launch(void* const* d_in, const int* in_sizes, int n_in,
                              void* d_out, int out_size)
{
    const float* x  = (const float*)d_in[0];
    const float* ox = (const float*)d_in[1];
    const float* oy = (const float*)d_in[2];
    const float* ua = (const float*)d_in[3];
    const float* us = (const float*)d_in[4];
    const float* ar = (const float*)d_in[5];
    const float* sr = (const float*)d_in[6];
    float* out = (float*)d_out;

    pre_kernel<<<NT_ + O_/8, 256>>>(x, ox, oy, ua, us, ar, sr);
    disp_kernel<<<dim3(H_ / 16, O_, B_), 256>>>(out);
}